// round 12
// baseline (speedup 1.0000x reference)
#include <cuda_runtime.h>
#include <cuda_fp16.h>
#include <cstdint>

// Ultimus R12: R8 proj/final (best measured). attn: 4 q-rows/thread to amortize
// LDS+loop issue overhead (FMA share of issue 81% -> 87%). KSPLIT=32 unchanged.

#define NROWS 8192
#define DIN   48
#define DA    8
#define KSPLIT 32
#define SPLIT 256
#define NPAIRS (SPLIT / 2)

typedef unsigned int u32;

__device__ __align__(16) __half g_k[NROWS * DA];   // Xk * log2e/sqrt(8)
__device__ __align__(16) __half g_q[NROWS * DA];
__device__ __align__(16) __half g_v[NROWS * DA];
__device__ __align__(16) float g_acc[KSPLIT * NROWS * DA];
__device__ float g_sum[KSPLIT * NROWS];

__device__ __forceinline__ u32 ex2h2(u32 s) {
    u32 r; asm("ex2.approx.f16x2 %0, %1;" : "=r"(r) : "r"(s)); return r;
}
__device__ __forceinline__ u32 prmt(u32 a, u32 b, u32 sel) {
    u32 r; asm("prmt.b32 %0, %1, %2, %3;" : "=r"(r) : "r"(a), "r"(b), "r"(sel)); return r;
}
__device__ __forceinline__ half2 h2(u32 v) { return *(half2*)&v; }
__device__ __forceinline__ u32 uu(half2 v) { return *(u32*)&v; }

// ---------------- Kernel 1: proj, 4 threads per (row, matrix) — R8 exact ----------------
__global__ __launch_bounds__(256) void proj_kernel(
    const float* __restrict__ x,
    const float* __restrict__ Kw, const float* __restrict__ Kb,
    const float* __restrict__ Qw, const float* __restrict__ Qb,
    const float* __restrict__ Vw, const float* __restrict__ Vb)
{
    __shared__ float sWc[DA * DIN];   // column-major: sWc[a*48 + d]
    __shared__ float sB[DA];
    int t = threadIdx.x;
    int which = blockIdx.y;
    const float* W = (which == 0) ? Kw : (which == 1) ? Qw : Vw;
    const float* B = (which == 0) ? Kb : (which == 1) ? Qb : Vb;
    for (int i = t; i < DA * DIN; i += 256) {
        int a = i / DIN, d = i - a * DIN;
        sWc[i] = W[d * DA + a];
    }
    if (t < DA) sB[t] = B[t];
    __syncthreads();

    float scale = (which == 0) ? (1.4426950408889634f / 2.8284271247461903f) : 1.0f;

    int row  = blockIdx.x * 64 + (t >> 2);
    int part = t & 3;

    const float4* xp = (const float4*)(x + (size_t)row * DIN) + part * 3;
    float4 x0 = xp[0], x1 = xp[1], x2 = xp[2];

    float acc[DA];
#pragma unroll
    for (int a = 0; a < DA; a++) {
        const float4* wp = (const float4*)(sWc + a * DIN + part * 12);
        float4 w0 = wp[0], w1 = wp[1], w2 = wp[2];
        float s0 = x0.x * w0.x;
        s0 = fmaf(x0.y, w0.y, s0);
        s0 = fmaf(x0.z, w0.z, s0);
        s0 = fmaf(x0.w, w0.w, s0);
        float s1 = x1.x * w1.x;
        s1 = fmaf(x1.y, w1.y, s1);
        s1 = fmaf(x1.z, w1.z, s1);
        s1 = fmaf(x1.w, w1.w, s1);
        float s2 = x2.x * w2.x;
        s2 = fmaf(x2.y, w2.y, s2);
        s2 = fmaf(x2.z, w2.z, s2);
        s2 = fmaf(x2.w, w2.w, s2);
        acc[a] = s0 + s1 + s2;
    }

#pragma unroll
    for (int a = 0; a < DA; a++) {
        acc[a] += __shfl_xor_sync(0xFFFFFFFFu, acc[a], 1);
        acc[a] += __shfl_xor_sync(0xFFFFFFFFu, acc[a], 2);
    }

    if (part == 0) {
        __half* dst = ((which == 0) ? g_k : (which == 1) ? g_q : g_v) + (size_t)row * DA;
        half2 h[4];
#pragma unroll
        for (int j = 0; j < 4; j++)
            h[j] = __floats2half2_rn((acc[2 * j] + sB[2 * j]) * scale,
                                     (acc[2 * j + 1] + sB[2 * j + 1]) * scale);
        *(uint4*)dst = *(uint4*)h;
    }
}

// ---------------- Kernel 2: fp16x2 attention, 4 rows/thread ----------------
__global__ __launch_bounds__(128, 4) void attn_kernel()
{
    __shared__ __align__(16) u32 sq[NPAIRS * 8];
    __shared__ __align__(16) u32 sv[NPAIRS * 8];

    int t = threadIdx.x;
    int rbase = blockIdx.x * 512 + t;
    int kbase = blockIdx.y * SPLIT;

    {
        const uint4* qp = (const uint4*)(g_q + (size_t)(kbase + 2 * t) * DA);
        uint4 q0 = qp[0], q1 = qp[1];
        ((uint4*)(sq + t * 8))[0] = make_uint4(prmt(q0.x, q1.x, 0x5410), prmt(q0.x, q1.x, 0x7632),
                                              prmt(q0.y, q1.y, 0x5410), prmt(q0.y, q1.y, 0x7632));
        ((uint4*)(sq + t * 8))[1] = make_uint4(prmt(q0.z, q1.z, 0x5410), prmt(q0.z, q1.z, 0x7632),
                                              prmt(q0.w, q1.w, 0x5410), prmt(q0.w, q1.w, 0x7632));
        const uint4* vp = (const uint4*)(g_v + (size_t)(kbase + 2 * t) * DA);
        uint4 v0 = vp[0], v1 = vp[1];
        ((uint4*)(sv + t * 8))[0] = make_uint4(prmt(v0.x, v1.x, 0x5410), prmt(v0.x, v1.x, 0x7632),
                                              prmt(v0.y, v1.y, 0x5410), prmt(v0.y, v1.y, 0x7632));
        ((uint4*)(sv + t * 8))[1] = make_uint4(prmt(v0.z, v1.z, 0x5410), prmt(v0.z, v1.z, 0x7632),
                                              prmt(v0.w, v1.w, 0x5410), prmt(v0.w, v1.w, 0x7632));
    }

    half2 kk[4][DA];
#pragma unroll
    for (int r = 0; r < 4; r++) {
        uint4 kr = *(const uint4*)(g_k + (size_t)(rbase + r * 128) * DA);
        half2* p = (half2*)&kr;
#pragma unroll
        for (int j = 0; j < 4; j++) {
            kk[r][2*j]   = __half2half2(__low2half(p[j]));
            kk[r][2*j+1] = __half2half2(__high2half(p[j]));
        }
    }

    float accF[4][DA];
    float ssumF[4];
#pragma unroll
    for (int r = 0; r < 4; r++) {
        ssumF[r] = 0.f;
#pragma unroll
        for (int a = 0; a < DA; a++) accF[r][a] = 0.f;
    }

    __syncthreads();

    const uint4* q4 = (const uint4*)sq;
    const uint4* v4 = (const uint4*)sv;

#pragma unroll
    for (int hlf = 0; hlf < 2; hlf++) {
        half2 acc[4][DA];
        half2 ssum[4];
#pragma unroll
        for (int r = 0; r < 4; r++) {
            ssum[r] = __floats2half2_rn(0.f, 0.f);
#pragma unroll
            for (int a = 0; a < DA; a++) acc[r][a] = __floats2half2_rn(0.f, 0.f);
        }

#pragma unroll 2
        for (int jp = hlf * (NPAIRS / 2); jp < (hlf + 1) * (NPAIRS / 2); jp++) {
            uint4 qA = q4[2 * jp], qB = q4[2 * jp + 1];
            half2 s[4];
#pragma unroll
            for (int r = 0; r < 4; r++) {
                half2 sr = __hmul2(kk[r][0], h2(qA.x));
                sr = __hfma2(kk[r][1], h2(qA.y), sr);
                sr = __hfma2(kk[r][2], h2(qA.z), sr);
                sr = __hfma2(kk[r][3], h2(qA.w), sr);
                sr = __hfma2(kk[r][4], h2(qB.x), sr);
                sr = __hfma2(kk[r][5], h2(qB.y), sr);
                sr = __hfma2(kk[r][6], h2(qB.z), sr);
                sr = __hfma2(kk[r][7], h2(qB.w), sr);
                s[r] = sr;
            }
            half2 p[4];
#pragma unroll
            for (int r = 0; r < 4; r++) {
                p[r] = h2(ex2h2(uu(s[r])));
                ssum[r] = __hadd2(ssum[r], p[r]);
            }
            uint4 vA = v4[2 * jp], vB = v4[2 * jp + 1];
#pragma unroll
            for (int r = 0; r < 4; r++) {
                acc[r][0] = __hfma2(p[r], h2(vA.x), acc[r][0]);
                acc[r][1] = __hfma2(p[r], h2(vA.y), acc[r][1]);
                acc[r][2] = __hfma2(p[r], h2(vA.z), acc[r][2]);
                acc[r][3] = __hfma2(p[r], h2(vA.w), acc[r][3]);
                acc[r][4] = __hfma2(p[r], h2(vB.x), acc[r][4]);
                acc[r][5] = __hfma2(p[r], h2(vB.y), acc[r][5]);
                acc[r][6] = __hfma2(p[r], h2(vB.z), acc[r][6]);
                acc[r][7] = __hfma2(p[r], h2(vB.w), acc[r][7]);
            }
        }

#pragma unroll
        for (int r = 0; r < 4; r++) {
#pragma unroll
            for (int a = 0; a < DA; a++) {
                float2 f = __half22float2(acc[r][a]);
                accF[r][a] += f.x + f.y;
            }
            float2 fs = __half22float2(ssum[r]);
            ssumF[r] += fs.x + fs.y;
        }
    }

#pragma unroll
    for (int r = 0; r < 4; r++) {
        int o = blockIdx.y * NROWS + rbase + r * 128;
        float4* ap = (float4*)(g_acc + (size_t)o * DA);
        ap[0] = make_float4(accF[r][0], accF[r][1], accF[r][2], accF[r][3]);
        ap[1] = make_float4(accF[r][4], accF[r][5], accF[r][6], accF[r][7]);
        g_sum[o] = ssumF[r];
    }
}

// ---------------- Kernel 3: final, 4 threads per row (R8 exact) ----------------
__global__ __launch_bounds__(128) void final_kernel(
    const float* __restrict__ x,
    const float* __restrict__ Zw, const float* __restrict__ Zb,
    float* __restrict__ out)
{
    __shared__ float sZ[DA * DIN];
    __shared__ float sZb[DIN];
    int t = threadIdx.x;
    for (int i = t; i < DA * DIN; i += 128) sZ[i] = Zw[i];
    if (t < DIN) sZb[t] = Zb[t];
    __syncthreads();

    int gid  = blockIdx.x * 128 + t;
    int row  = gid >> 2;
    int part = gid & 3;

    float acc[DA];
#pragma unroll
    for (int a = 0; a < DA; a++) acc[a] = 0.0f;
    float ssum = 0.0f;
#pragma unroll
    for (int i = 0; i < KSPLIT / 4; i++) {
        int o = (part * (KSPLIT / 4) + i) * NROWS + row;
        ssum += g_sum[o];
        const float4* ap = (const float4*)(g_acc + (size_t)o * DA);
        float4 a0 = ap[0], a1 = ap[1];
        acc[0] += a0.x; acc[1] += a0.y; acc[2] += a0.z; acc[3] += a0.w;
        acc[4] += a1.x; acc[5] += a1.y; acc[6] += a1.z; acc[7] += a1.w;
    }
#pragma unroll
    for (int a = 0; a < DA; a++) {
        acc[a] += __shfl_xor_sync(0xFFFFFFFFu, acc[a], 1);
        acc[a] += __shfl_xor_sync(0xFFFFFFFFu, acc[a], 2);
    }
    ssum += __shfl_xor_sync(0xFFFFFFFFu, ssum, 1);
    ssum += __shfl_xor_sync(0xFFFFFFFFu, ssum, 2);

    float inv = 1.0f / ssum;
    float z[DA];
#pragma unroll
    for (int a = 0; a < DA; a++) z[a] = acc[a] * inv;

    const float4* xp = (const float4*)(x + (size_t)row * DIN) + part * 3;
    float4* op = (float4*)(out + (size_t)row * DIN) + part * 3;
#pragma unroll
    for (int c = 0; c < 3; c++) {
        int d0 = part * 12 + 4 * c;
        float4 xv = xp[c];
        float o4[4] = {xv.x + sZb[d0], xv.y + sZb[d0 + 1], xv.z + sZb[d0 + 2], xv.w + sZb[d0 + 3]};
#pragma unroll
        for (int a = 0; a < DA; a++) {
            float za = z[a];
            const float* w = &sZ[a * DIN + d0];
            o4[0] = fmaf(za, w[0], o4[0]);
            o4[1] = fmaf(za, w[1], o4[1]);
            o4[2] = fmaf(za, w[2], o4[2]);
            o4[3] = fmaf(za, w[3], o4[3]);
        }
        op[c] = make_float4(o4[0], o4[1], o4[2], o4[3]);
    }
}

extern "C" void kernel_launch(void* const* d_in, const int* in_sizes, int n_in,
                              void* d_out, int out_size)
{
    (void)in_sizes; (void)n_in; (void)out_size;
    const float* x  = (const float*)d_in[0];
    const float* Kw = (const float*)d_in[1];
    const float* Kb = (const float*)d_in[2];
    const float* Qw = (const float*)d_in[3];
    const float* Qb = (const float*)d_in[4];
    const float* Vw = (const float*)d_in[5];
    const float* Vb = (const float*)d_in[6];
    const float* Zw = (const float*)d_in[7];
    const float* Zb = (const float*)d_in[8];
    float* out = (float*)d_out;

    dim3 gp(NROWS / 64, 3);
    proj_kernel<<<gp, 256>>>(x, Kw, Kb, Qw, Qb, Vw, Vb);
    dim3 ga(NROWS / 512, KSPLIT);
    attn_kernel<<<ga, 128>>>();
    final_kernel<<<(NROWS * 4) / 128, 128>>>(x, Zw, Zb, out);
}

// round 13
// speedup vs baseline: 1.0861x; 1.0861x over previous
#include <cuda_runtime.h>
#include <cuda_fp16.h>
#include <cstdint>

// Ultimus R13: R8 exact (best measured, 47.6us) with one change: proj issues its
// x LDGs BEFORE weight staging/sync so DRAM latency overlaps staging (front-batch).

#define NROWS 8192
#define DIN   48
#define DA    8
#define KSPLIT 32
#define SPLIT 256
#define NPAIRS (SPLIT / 2)

typedef unsigned int u32;

__device__ __align__(16) __half g_k[NROWS * DA];   // Xk * log2e/sqrt(8)
__device__ __align__(16) __half g_q[NROWS * DA];
__device__ __align__(16) __half g_v[NROWS * DA];
__device__ __align__(16) float g_acc[KSPLIT * NROWS * DA];
__device__ float g_sum[KSPLIT * NROWS];

__device__ __forceinline__ u32 ex2h2(u32 s) {
    u32 r; asm("ex2.approx.f16x2 %0, %1;" : "=r"(r) : "r"(s)); return r;
}
__device__ __forceinline__ u32 prmt(u32 a, u32 b, u32 sel) {
    u32 r; asm("prmt.b32 %0, %1, %2, %3;" : "=r"(r) : "r"(a), "r"(b), "r"(sel)); return r;
}
__device__ __forceinline__ half2 h2(u32 v) { return *(half2*)&v; }
__device__ __forceinline__ u32 uu(half2 v) { return *(u32*)&v; }

// ---------------- Kernel 1: proj, 4 threads per (row, matrix); x loads hoisted ----------------
__global__ __launch_bounds__(256) void proj_kernel(
    const float* __restrict__ x,
    const float* __restrict__ Kw, const float* __restrict__ Kb,
    const float* __restrict__ Qw, const float* __restrict__ Qb,
    const float* __restrict__ Vw, const float* __restrict__ Vb)
{
    __shared__ float sWc[DA * DIN];   // column-major: sWc[a*48 + d]
    __shared__ float sB[DA];
    int t = threadIdx.x;

    // issue x loads FIRST (independent of smem) so DRAM latency overlaps staging+BAR
    int row  = blockIdx.x * 64 + (t >> 2);
    int part = t & 3;
    const float4* xp = (const float4*)(x + (size_t)row * DIN) + part * 3;
    float4 x0 = xp[0], x1 = xp[1], x2 = xp[2];

    int which = blockIdx.y;
    const float* W = (which == 0) ? Kw : (which == 1) ? Qw : Vw;
    const float* B = (which == 0) ? Kb : (which == 1) ? Qb : Vb;
    for (int i = t; i < DA * DIN; i += 256) {
        int a = i / DIN, d = i - a * DIN;
        sWc[i] = W[d * DA + a];
    }
    if (t < DA) sB[t] = B[t];
    __syncthreads();

    float scale = (which == 0) ? (1.4426950408889634f / 2.8284271247461903f) : 1.0f;

    float acc[DA];
#pragma unroll
    for (int a = 0; a < DA; a++) {
        const float4* wp = (const float4*)(sWc + a * DIN + part * 12);
        float4 w0 = wp[0], w1 = wp[1], w2 = wp[2];
        float s0 = x0.x * w0.x;
        s0 = fmaf(x0.y, w0.y, s0);
        s0 = fmaf(x0.z, w0.z, s0);
        s0 = fmaf(x0.w, w0.w, s0);
        float s1 = x1.x * w1.x;
        s1 = fmaf(x1.y, w1.y, s1);
        s1 = fmaf(x1.z, w1.z, s1);
        s1 = fmaf(x1.w, w1.w, s1);
        float s2 = x2.x * w2.x;
        s2 = fmaf(x2.y, w2.y, s2);
        s2 = fmaf(x2.z, w2.z, s2);
        s2 = fmaf(x2.w, w2.w, s2);
        acc[a] = s0 + s1 + s2;
    }

#pragma unroll
    for (int a = 0; a < DA; a++) {
        acc[a] += __shfl_xor_sync(0xFFFFFFFFu, acc[a], 1);
        acc[a] += __shfl_xor_sync(0xFFFFFFFFu, acc[a], 2);
    }

    if (part == 0) {
        __half* dst = ((which == 0) ? g_k : (which == 1) ? g_q : g_v) + (size_t)row * DA;
        half2 h[4];
#pragma unroll
        for (int j = 0; j < 4; j++)
            h[j] = __floats2half2_rn((acc[2 * j] + sB[2 * j]) * scale,
                                     (acc[2 * j + 1] + sB[2 * j + 1]) * scale);
        *(uint4*)dst = *(uint4*)h;
    }
}

// ---------------- Kernel 2: fp16x2 attention, one staged 256-key split (R8 exact) ----------------
__global__ __launch_bounds__(128) void attn_kernel()
{
    __shared__ __align__(16) u32 sq[NPAIRS * 8];
    __shared__ __align__(16) u32 sv[NPAIRS * 8];

    int t = threadIdx.x;
    int r0 = blockIdx.x * 256 + t;
    int r1 = r0 + 128;
    int kbase = blockIdx.y * SPLIT;

    {
        const uint4* qp = (const uint4*)(g_q + (size_t)(kbase + 2 * t) * DA);
        uint4 q0 = qp[0], q1 = qp[1];
        ((uint4*)(sq + t * 8))[0] = make_uint4(prmt(q0.x, q1.x, 0x5410), prmt(q0.x, q1.x, 0x7632),
                                              prmt(q0.y, q1.y, 0x5410), prmt(q0.y, q1.y, 0x7632));
        ((uint4*)(sq + t * 8))[1] = make_uint4(prmt(q0.z, q1.z, 0x5410), prmt(q0.z, q1.z, 0x7632),
                                              prmt(q0.w, q1.w, 0x5410), prmt(q0.w, q1.w, 0x7632));
        const uint4* vp = (const uint4*)(g_v + (size_t)(kbase + 2 * t) * DA);
        uint4 v0 = vp[0], v1 = vp[1];
        ((uint4*)(sv + t * 8))[0] = make_uint4(prmt(v0.x, v1.x, 0x5410), prmt(v0.x, v1.x, 0x7632),
                                              prmt(v0.y, v1.y, 0x5410), prmt(v0.y, v1.y, 0x7632));
        ((uint4*)(sv + t * 8))[1] = make_uint4(prmt(v0.z, v1.z, 0x5410), prmt(v0.z, v1.z, 0x7632),
                                              prmt(v0.w, v1.w, 0x5410), prmt(v0.w, v1.w, 0x7632));
    }

    half2 kk0[DA], kk1[DA];
    {
        uint4 kr0 = *(const uint4*)(g_k + (size_t)r0 * DA);
        uint4 kr1 = *(const uint4*)(g_k + (size_t)r1 * DA);
        half2* p0 = (half2*)&kr0;
        half2* p1 = (half2*)&kr1;
#pragma unroll
        for (int j = 0; j < 4; j++) {
            kk0[2*j]   = __half2half2(__low2half(p0[j]));
            kk0[2*j+1] = __half2half2(__high2half(p0[j]));
            kk1[2*j]   = __half2half2(__low2half(p1[j]));
            kk1[2*j+1] = __half2half2(__high2half(p1[j]));
        }
    }

    float accF0[DA], accF1[DA];
#pragma unroll
    for (int a = 0; a < DA; a++) { accF0[a] = 0.f; accF1[a] = 0.f; }
    float ssumF0 = 0.f, ssumF1 = 0.f;

    __syncthreads();

    const uint4* q4 = (const uint4*)sq;
    const uint4* v4 = (const uint4*)sv;

#pragma unroll
    for (int hlf = 0; hlf < 2; hlf++) {
        half2 acc0[DA], acc1[DA];
#pragma unroll
        for (int a = 0; a < DA; a++) { acc0[a] = __floats2half2_rn(0.f, 0.f); acc1[a] = acc0[a]; }
        half2 ssum0 = __floats2half2_rn(0.f, 0.f), ssum1 = ssum0;

#pragma unroll 4
        for (int jp = hlf * (NPAIRS / 2); jp < (hlf + 1) * (NPAIRS / 2); jp++) {
            uint4 qA = q4[2 * jp], qB = q4[2 * jp + 1];
            half2 s0 = __hmul2(kk0[0], h2(qA.x));
            half2 s1 = __hmul2(kk1[0], h2(qA.x));
            s0 = __hfma2(kk0[1], h2(qA.y), s0);  s1 = __hfma2(kk1[1], h2(qA.y), s1);
            s0 = __hfma2(kk0[2], h2(qA.z), s0);  s1 = __hfma2(kk1[2], h2(qA.z), s1);
            s0 = __hfma2(kk0[3], h2(qA.w), s0);  s1 = __hfma2(kk1[3], h2(qA.w), s1);
            s0 = __hfma2(kk0[4], h2(qB.x), s0);  s1 = __hfma2(kk1[4], h2(qB.x), s1);
            s0 = __hfma2(kk0[5], h2(qB.y), s0);  s1 = __hfma2(kk1[5], h2(qB.y), s1);
            s0 = __hfma2(kk0[6], h2(qB.z), s0);  s1 = __hfma2(kk1[6], h2(qB.z), s1);
            s0 = __hfma2(kk0[7], h2(qB.w), s0);  s1 = __hfma2(kk1[7], h2(qB.w), s1);
            half2 p0 = h2(ex2h2(uu(s0)));
            half2 p1 = h2(ex2h2(uu(s1)));
            ssum0 = __hadd2(ssum0, p0);
            ssum1 = __hadd2(ssum1, p1);
            uint4 vA = v4[2 * jp], vB = v4[2 * jp + 1];
            acc0[0] = __hfma2(p0, h2(vA.x), acc0[0]);  acc1[0] = __hfma2(p1, h2(vA.x), acc1[0]);
            acc0[1] = __hfma2(p0, h2(vA.y), acc0[1]);  acc1[1] = __hfma2(p1, h2(vA.y), acc1[1]);
            acc0[2] = __hfma2(p0, h2(vA.z), acc0[2]);  acc1[2] = __hfma2(p1, h2(vA.z), acc1[2]);
            acc0[3] = __hfma2(p0, h2(vA.w), acc0[3]);  acc1[3] = __hfma2(p1, h2(vA.w), acc1[3]);
            acc0[4] = __hfma2(p0, h2(vB.x), acc0[4]);  acc1[4] = __hfma2(p1, h2(vB.x), acc1[4]);
            acc0[5] = __hfma2(p0, h2(vB.y), acc0[5]);  acc1[5] = __hfma2(p1, h2(vB.y), acc1[5]);
            acc0[6] = __hfma2(p0, h2(vB.z), acc0[6]);  acc1[6] = __hfma2(p1, h2(vB.z), acc1[6]);
            acc0[7] = __hfma2(p0, h2(vB.w), acc0[7]);  acc1[7] = __hfma2(p1, h2(vB.w), acc1[7]);
        }

#pragma unroll
        for (int a = 0; a < DA; a++) {
            float2 f0 = __half22float2(acc0[a]);
            float2 f1 = __half22float2(acc1[a]);
            accF0[a] += f0.x + f0.y;
            accF1[a] += f1.x + f1.y;
        }
        float2 fs0 = __half22float2(ssum0);
        float2 fs1 = __half22float2(ssum1);
        ssumF0 += fs0.x + fs0.y;
        ssumF1 += fs1.x + fs1.y;
    }

    int o0 = blockIdx.y * NROWS + r0;
    int o1 = blockIdx.y * NROWS + r1;
    float4* ap0 = (float4*)(g_acc + (size_t)o0 * DA);
    float4* ap1 = (float4*)(g_acc + (size_t)o1 * DA);
    ap0[0] = make_float4(accF0[0], accF0[1], accF0[2], accF0[3]);
    ap0[1] = make_float4(accF0[4], accF0[5], accF0[6], accF0[7]);
    ap1[0] = make_float4(accF1[0], accF1[1], accF1[2], accF1[3]);
    ap1[1] = make_float4(accF1[4], accF1[5], accF1[6], accF1[7]);
    g_sum[o0] = ssumF0;
    g_sum[o1] = ssumF1;
}

// ---------------- Kernel 3: final, 4 threads per row (R8 exact) ----------------
__global__ __launch_bounds__(128) void final_kernel(
    const float* __restrict__ x,
    const float* __restrict__ Zw, const float* __restrict__ Zb,
    float* __restrict__ out)
{
    __shared__ float sZ[DA * DIN];
    __shared__ float sZb[DIN];
    int t = threadIdx.x;
    for (int i = t; i < DA * DIN; i += 128) sZ[i] = Zw[i];
    if (t < DIN) sZb[t] = Zb[t];
    __syncthreads();

    int gid  = blockIdx.x * 128 + t;
    int row  = gid >> 2;
    int part = gid & 3;

    float acc[DA];
#pragma unroll
    for (int a = 0; a < DA; a++) acc[a] = 0.0f;
    float ssum = 0.0f;
#pragma unroll
    for (int i = 0; i < KSPLIT / 4; i++) {
        int o = (part * (KSPLIT / 4) + i) * NROWS + row;
        ssum += g_sum[o];
        const float4* ap = (const float4*)(g_acc + (size_t)o * DA);
        float4 a0 = ap[0], a1 = ap[1];
        acc[0] += a0.x; acc[1] += a0.y; acc[2] += a0.z; acc[3] += a0.w;
        acc[4] += a1.x; acc[5] += a1.y; acc[6] += a1.z; acc[7] += a1.w;
    }
#pragma unroll
    for (int a = 0; a < DA; a++) {
        acc[a] += __shfl_xor_sync(0xFFFFFFFFu, acc[a], 1);
        acc[a] += __shfl_xor_sync(0xFFFFFFFFu, acc[a], 2);
    }
    ssum += __shfl_xor_sync(0xFFFFFFFFu, ssum, 1);
    ssum += __shfl_xor_sync(0xFFFFFFFFu, ssum, 2);

    float inv = 1.0f / ssum;
    float z[DA];
#pragma unroll
    for (int a = 0; a < DA; a++) z[a] = acc[a] * inv;

    const float4* xp = (const float4*)(x + (size_t)row * DIN) + part * 3;
    float4* op = (float4*)(out + (size_t)row * DIN) + part * 3;
#pragma unroll
    for (int c = 0; c < 3; c++) {
        int d0 = part * 12 + 4 * c;
        float4 xv = xp[c];
        float o4[4] = {xv.x + sZb[d0], xv.y + sZb[d0 + 1], xv.z + sZb[d0 + 2], xv.w + sZb[d0 + 3]};
#pragma unroll
        for (int a = 0; a < DA; a++) {
            float za = z[a];
            const float* w = &sZ[a * DIN + d0];
            o4[0] = fmaf(za, w[0], o4[0]);
            o4[1] = fmaf(za, w[1], o4[1]);
            o4[2] = fmaf(za, w[2], o4[2]);
            o4[3] = fmaf(za, w[3], o4[3]);
        }
        op[c] = make_float4(o4[0], o4[1], o4[2], o4[3]);
    }
}

extern "C" void kernel_launch(void* const* d_in, const int* in_sizes, int n_in,
                              void* d_out, int out_size)
{
    (void)in_sizes; (void)n_in; (void)out_size;
    const float* x  = (const float*)d_in[0];
    const float* Kw = (const float*)d_in[1];
    const float* Kb = (const float*)d_in[2];
    const float* Qw = (const float*)d_in[3];
    const float* Qb = (const float*)d_in[4];
    const float* Vw = (const float*)d_in[5];
    const float* Vb = (const float*)d_in[6];
    const float* Zw = (const float*)d_in[7];
    const float* Zb = (const float*)d_in[8];
    float* out = (float*)d_out;

    dim3 gp(NROWS / 64, 3);
    proj_kernel<<<gp, 256>>>(x, Kw, Kb, Qw, Qb, Vw, Vb);
    dim3 ga(NROWS / 256, KSPLIT);
    attn_kernel<<<ga, 128>>>();
    final_kernel<<<(NROWS * 4) / 128, 128>>>(x, Zw, Zb, out);
}